// round 5
// baseline (speedup 1.0000x reference)
#include <cuda_runtime.h>
#include <cuda_fp16.h>
#include <cstdint>

// ---------------------------------------------------------------------------
// VectorQuantize via mma.sync.m16n8k16.f16 (3xFP16 emulated fp32) + exact
// fp32 rescore. All MMA operand fetches are LDS.128 via hi/lo interleaving.
// ---------------------------------------------------------------------------

#define NCODES 8192
#define OFF_Q     0
#define OFF_IND   2097152
#define OFF_LOSS  2129920
#define OFF_NC    2129921
#define OFF_EA    2138113
#define OFF_NE    2662401
#define OUT_FULL  3186689

#define RPB    128
#define NTILES 64

// smem word offsets
#define W_A    0        // 2048 uint4: [4 kc16][128 row][4 kl] hi/lo interleaved
#define W_B    8192     // 2 stages x 2048 uint4: [kc16][col][kl]
#define W_CN   24576    // 2 x 128
#define W_IND  24832
#define W_RED  24960    // 2 halves x 128 float2
#define W_LOSS 25472
#define SMEM_TOTAL 101920

// device scratch
__device__ float g_pe[65536];
__device__ __align__(16) float g_cn[NCODES];
__device__ float g_counts[NCODES];
__device__ float g_esum[64 * NCODES];
__device__ __align__(16) float g_et[NCODES * 64];    // E^T fp32 [j][k]
__device__ __align__(16) uint4 g_ei[NCODES * 16];    // interleaved hi/lo frags
__device__ float g_loss, g_total;

// ---------------------------------------------------------------------------
__device__ __forceinline__ uint32_t smem_u32(const void* p) {
    uint32_t a;
    asm("{ .reg .u64 t; cvta.to.shared.u64 t, %1; cvt.u32.u64 %0, t; }"
        : "=r"(a) : "l"(p));
    return a;
}
__device__ __forceinline__ void mma16(float* d, uint32_t a0, uint32_t a1,
                                      uint32_t a2, uint32_t a3,
                                      uint32_t b0, uint32_t b1) {
    asm volatile(
        "mma.sync.aligned.m16n8k16.row.col.f32.f16.f16.f32 "
        "{%0,%1,%2,%3}, {%4,%5,%6,%7}, {%8,%9}, {%0,%1,%2,%3};"
        : "+f"(d[0]), "+f"(d[1]), "+f"(d[2]), "+f"(d[3])
        : "r"(a0), "r"(a1), "r"(a2), "r"(a3), "r"(b0), "r"(b1));
}
__device__ __forceinline__ void cp16(uint32_t dst, const void* src) {
    asm volatile("cp.async.cg.shared.global [%0], [%1], 16;"
                 :: "r"(dst), "l"(src) : "memory");
}
#define CP_COMMIT() asm volatile("cp.async.commit_group;" ::: "memory")
#define CP_WAIT1()  asm volatile("cp.async.wait_group 1;" ::: "memory")

__device__ __forceinline__ uint32_t pkh(float a, float b) {
    __half2 h = __floats2half2_rn(a, b);
    return *(uint32_t*)&h;
}

// ---------------------------------------------------------------------------
// prep0: PE table, zero scratch.  grid 2048 x 256
// ---------------------------------------------------------------------------
__global__ void vq_prep0(const float* __restrict__ pos_emb) {
    int idx = blockIdx.x * 256 + threadIdx.x;
    g_esum[idx] = 0.0f;
    if (idx < 65536) {
        int jj = idx & 63, i = (idx >> 6) & 63, c = idx >> 12;
        int s = ((i >> 2) << 4) + (jj >> 2);
        int d = (c << 4) + ((i & 3) << 2) + (jj & 3);
        g_pe[idx] = pos_emb[s * 256 + d];
    }
    if (idx < NCODES) g_counts[idx] = 0.0f;
    if (idx == 0) { g_loss = 0.0f; g_total = 0.0f; }
}

// ---------------------------------------------------------------------------
// prep1: transpose embed -> g_et, interleaved fp16 hi/lo frags, code norms.
// grid 64 x 256 (block = 128 codes).
// ---------------------------------------------------------------------------
__global__ void vq_prep1(const float* __restrict__ embed) {
    __shared__ float sE[64][129];
    __shared__ float scn[128][2];
    const int tid = threadIdx.x;
    const int j0 = blockIdx.x * 128;
#pragma unroll 4
    for (int kk = 0; kk < 32; kk++) {
        int k = kk * 2 + (tid >> 7);
        int jl = tid & 127;
        sE[k][jl] = embed[(size_t)k * NCODES + j0 + jl];
    }
    __syncthreads();
    const int jl = tid & 127, kh = tid >> 7;
    const int j = j0 + jl;
    float ssum = 0.0f;
#pragma unroll
    for (int kc = 2 * kh; kc <= 2 * kh + 1; kc++) {
        uint32_t hw[8], lw[8];
#pragma unroll
        for (int w = 0; w < 8; w++) {
            int k = kc * 16 + 2 * w;
            float v0 = sE[k][jl], v1 = sE[k + 1][jl];
            ssum += v0 * v0 + v1 * v1;
            *(float2*)(g_et + (size_t)j * 64 + k) = make_float2(v0, v1);
            __half h0 = __float2half_rn(v0), h1 = __float2half_rn(v1);
            float l0 = v0 - __half2float(h0), l1 = v1 - __half2float(h1);
            hw[w] = pkh(__half2float(h0), __half2float(h1));
            lw[w] = pkh(l0, l1);
        }
#pragma unroll
        for (int kl = 0; kl < 4; kl++)
            g_ei[(size_t)j * 16 + kc * 4 + kl] =
                make_uint4(hw[kl], hw[kl + 4], lw[kl], lw[kl + 4]);
    }
    scn[jl][kh] = ssum;
    __syncthreads();
    if (tid < 128) g_cn[j0 + tid] = -0.5f * (scn[tid][0] + scn[tid][1]);
}

// ---------------------------------------------------------------------------
// async B tile: g_ei -> smem [kc16][col][kl] (1:1 16B chunks)
// ---------------------------------------------------------------------------
__device__ __forceinline__ void load_b_tile(uint32_t smem_base, int t, int tid) {
    const int cb = t * 128;
    const uint32_t bb = smem_base + (uint32_t)(W_B + (t & 1) * 8192) * 4u;
#pragma unroll
    for (int i = 0; i < 8; i++) {
        int c = tid + (i << 8);             // 0..2047 uint4 chunks
        int kc16 = c >> 9, col = (c >> 2) & 127, kl = c & 3;
        const uint4* src = g_ei + (size_t)(cb + col) * 16 + kc16 * 4 + kl;
        cp16(bb + (uint32_t)c * 16u, src);
    }
    if (tid < 32)
        cp16(smem_base + (uint32_t)(W_CN + (t & 1) * 128) * 4u + tid * 16,
             g_cn + cb + tid * 4);
}

// ---------------------------------------------------------------------------
// main: 256 CTAs x 256 threads, 2 CTAs/SM. warp tile 32x64, 3xFP16 mma.
// ---------------------------------------------------------------------------
__global__ void __launch_bounds__(256, 2)
vq_main(const float* __restrict__ input, float* __restrict__ out, int full) {
    extern __shared__ float smf[];
    const uint32_t smem_base = smem_u32(smf);
    const int tid = threadIdx.x, wid = tid >> 5, lane = tid & 31;
    const int wr = wid >> 1, wc = wid & 1;
    const int g = lane >> 2, kl = lane & 3;
    const int row0 = blockIdx.x * RPB;

    int* IndSh = (int*)(smf + W_IND);
    float2* RED = (float2*)(smf + W_RED);
    uint4* A4 = (uint4*)(smf + W_A);
    if (tid == 0) smf[W_LOSS] = 0.0f;

    // ---- A build: X = input + pe, interleaved hi/lo uint4 frags ----
    {
        int row = tid >> 1, h = tid & 1, rg = row0 + row;
        const float4* ip = (const float4*)(input + (size_t)rg * 64);
        const float4* pp = (const float4*)(g_pe + (size_t)(rg & 1023) * 64);
#pragma unroll
        for (int kc = 2 * h; kc <= 2 * h + 1; kc++) {
            uint32_t hw[8], lw[8];
#pragma unroll
            for (int qq = 0; qq < 4; qq++) {
                float4 a = ip[kc * 4 + qq], b = pp[kc * 4 + qq];
                float x0 = a.x + b.x, x1 = a.y + b.y;
                float x2 = a.z + b.z, x3 = a.w + b.w;
                __half h0 = __float2half_rn(x0), h1 = __float2half_rn(x1);
                __half h2 = __float2half_rn(x2), h3 = __float2half_rn(x3);
                hw[2 * qq]     = pkh(__half2float(h0), __half2float(h1));
                hw[2 * qq + 1] = pkh(__half2float(h2), __half2float(h3));
                lw[2 * qq]     = pkh(x0 - __half2float(h0), x1 - __half2float(h1));
                lw[2 * qq + 1] = pkh(x2 - __half2float(h2), x3 - __half2float(h3));
            }
            int sz = (row & 3) ^ (kc >> 1);
#pragma unroll
            for (int klx = 0; klx < 4; klx++)
                A4[kc * 512 + row * 4 + (klx ^ sz)] =
                    make_uint4(hw[klx], hw[klx + 4], lw[klx], lw[klx + 4]);
        }
    }
    load_b_tile(smem_base, 0, tid); CP_COMMIT();
    load_b_tile(smem_base, 1, tid); CP_COMMIT();

    float best[4];
    int bcol[4];
#pragma unroll
    for (int s = 0; s < 4; s++) { best[s] = -3.4e38f; bcol[s] = 0; }

    for (int t = 0; t < NTILES; t++) {
        CP_WAIT1();
        __syncthreads();
        const uint4* B4 = (const uint4*)(smf + W_B + (t & 1) * 8192);
        const float* cn = smf + W_CN + (t & 1) * 128 + wc * 64;

        float acc[2][8][4];
#pragma unroll
        for (int nf = 0; nf < 8; nf++) {
            float c0 = cn[nf * 8 + 2 * kl];
            float c1 = cn[nf * 8 + 2 * kl + 1];
#pragma unroll
            for (int m = 0; m < 2; m++) {
                acc[m][nf][0] = c0; acc[m][nf][1] = c1;
                acc[m][nf][2] = c0; acc[m][nf][3] = c1;
            }
        }
#pragma unroll
        for (int kc16 = 0; kc16 < 4; kc16++) {
            const int klA = kl ^ (g & 3) ^ (kc16 >> 1);
            uint4 a0[2], a1[2];
#pragma unroll
            for (int m = 0; m < 2; m++) {
                int r0 = wr * 32 + m * 16 + g;
                a0[m] = A4[kc16 * 512 + r0 * 4 + klA];
                a1[m] = A4[kc16 * 512 + (r0 + 8) * 4 + klA];
            }
#pragma unroll
            for (int nf = 0; nf < 8; nf++) {
                uint4 b = B4[kc16 * 512 + (wc * 64 + nf * 8 + g) * 4 + kl];
#pragma unroll
                for (int m = 0; m < 2; m++) {
                    mma16(acc[m][nf], a0[m].x, a1[m].x, a0[m].y, a1[m].y, b.x, b.y);
                    mma16(acc[m][nf], a0[m].x, a1[m].x, a0[m].y, a1[m].y, b.z, b.w);
                    mma16(acc[m][nf], a0[m].z, a1[m].z, a0[m].w, a1[m].w, b.x, b.y);
                }
            }
        }
        // argmax: one index-carrying pairwise max level, then short chain
        int colbase0 = t * 128 + wc * 64 + 2 * kl;
#pragma unroll
        for (int m = 0; m < 2; m++) {
#pragma unroll
            for (int nf = 0; nf < 8; nf++) {
                int c01 = colbase0 + nf * 8;
                float v0 = acc[m][nf][0], v1 = acc[m][nf][1];
                float v2 = acc[m][nf][2], v3 = acc[m][nf][3];
                float m0 = fmaxf(v0, v1);
                int cm0 = (v1 > v0) ? c01 + 1 : c01;
                float m1 = fmaxf(v2, v3);
                int cm1 = (v3 > v2) ? c01 + 1 : c01;
                int s0 = 2 * m, s1 = 2 * m + 1;
                if (m0 > best[s0]) { best[s0] = m0; bcol[s0] = cm0; }
                if (m1 > best[s1]) { best[s1] = m1; bcol[s1] = cm1; }
            }
        }
        __syncthreads();
        if (t + 2 < NTILES) load_b_tile(smem_base, t + 2, tid);
        CP_COMMIT();
    }

    // ---- quad reduce ----
#pragma unroll
    for (int s = 0; s < 4; s++) {
        float v = best[s];
        int c = bcol[s];
#pragma unroll
        for (int off = 1; off <= 2; off <<= 1) {
            float ov = __shfl_xor_sync(0xffffffffu, v, off);
            int oc = __shfl_xor_sync(0xffffffffu, c, off);
            if (ov > v || (ov == v && oc < c)) { v = ov; c = oc; }
        }
        if ((lane & 3) == 0) {
            int rowl = wr * 32 + (s >> 1) * 16 + (s & 1) * 8 + g;
            RED[wc * 128 + rowl] = make_float2(v, __int_as_float(c));
        }
    }
    __syncthreads();

    // ---- exact fp32 rescore of the two half-winners per row ----
    if (tid < 128) {
        int row = tid, rg = row0 + row;
        float xv[64];
        const float4* ip = (const float4*)(input + (size_t)rg * 64);
        const float4* pp = (const float4*)(g_pe + (size_t)(rg & 1023) * 64);
#pragma unroll
        for (int q = 0; q < 16; q++) {
            float4 a = ip[q], b = pp[q];
            xv[q * 4 + 0] = a.x + b.x; xv[q * 4 + 1] = a.y + b.y;
            xv[q * 4 + 2] = a.z + b.z; xv[q * 4 + 3] = a.w + b.w;
        }
        int c0 = __float_as_int(RED[row].y);
        int c1 = __float_as_int(RED[128 + row].y);
        float s0 = g_cn[c0], s1 = g_cn[c1];
        const float4* e0 = (const float4*)(g_et + (size_t)c0 * 64);
        const float4* e1 = (const float4*)(g_et + (size_t)c1 * 64);
#pragma unroll
        for (int q = 0; q < 16; q++) {
            float4 ea = e0[q], eb = e1[q];
            s0 = fmaf(xv[q * 4 + 0], ea.x, s0); s0 = fmaf(xv[q * 4 + 1], ea.y, s0);
            s0 = fmaf(xv[q * 4 + 2], ea.z, s0); s0 = fmaf(xv[q * 4 + 3], ea.w, s0);
            s1 = fmaf(xv[q * 4 + 0], eb.x, s1); s1 = fmaf(xv[q * 4 + 1], eb.y, s1);
            s1 = fmaf(xv[q * 4 + 2], eb.z, s1); s1 = fmaf(xv[q * 4 + 3], eb.w, s1);
        }
        int bj = (s1 > s0 || (s1 == s0 && c1 < c0)) ? c1 : c0;
        IndSh[row] = bj;
        if (full) out[OFF_IND + rg] = (float)bj;
        atomicAdd(&g_counts[bj], 1.0f);
    }
    __syncthreads();

    // ---- epilogue: quantize gather, loss, embed_sum scatter ----
    {
        float lsum = 0.0f;
        for (int it = 0; it < 16; it++) {
            int rloc = wid * 16 + it;
            int rg = row0 + rloc;
            int j = IndSh[rloc];
#pragma unroll
            for (int h2 = 0; h2 < 2; h2++) {
                int k = lane + 32 * h2;
                float ev = g_et[(size_t)j * 64 + k];
                float iv = input[(size_t)rg * 64 + k];
                float dd = ev - iv;
                lsum += dd * dd;
                out[OFF_Q + (size_t)rg * 64 + k] = ev;
                float xv2 = iv + g_pe[(rg & 1023) * 64 + k];
                atomicAdd(&g_esum[(size_t)k * NCODES + j], xv2);
            }
        }
#pragma unroll
        for (int off = 16; off; off >>= 1)
            lsum += __shfl_down_sync(0xffffffffu, lsum, off);
        if (lane == 0) atomicAdd(smf + W_LOSS, lsum);
    }
    __syncthreads();
    if (tid == 0) atomicAdd(&g_loss, smf[W_LOSS]);
}

// ---------------------------------------------------------------------------
__global__ void vq_fin1(const float* __restrict__ cs, float* __restrict__ out) {
    int j = blockIdx.x * 256 + threadIdx.x;
    float nc = 0.8f * cs[j] + 0.2f * g_counts[j];
    out[OFF_NC + j] = nc;
    __shared__ float sh[256];
    sh[threadIdx.x] = nc;
    __syncthreads();
    for (int s = 128; s; s >>= 1) {
        if (threadIdx.x < s) sh[threadIdx.x] += sh[threadIdx.x + s];
        __syncthreads();
    }
    if (threadIdx.x == 0) atomicAdd(&g_total, sh[0]);
}

__global__ void vq_fin2(const float* __restrict__ ea, float* __restrict__ out) {
    int idx = blockIdx.x * 256 + threadIdx.x;
    int j = idx & (NCODES - 1);
    float nea = 0.8f * ea[idx] + 0.2f * g_esum[idx];
    out[OFF_EA + idx] = nea;
    float total = g_total;
    float nc = out[OFF_NC + j];
    float smoothed = (nc + 1e-5f) / (total + NCODES * 1e-5f) * total;
    out[OFF_NE + idx] = nea / smoothed;
    if (idx == 0) out[OFF_LOSS] = g_loss * (1.0f / 2097152.0f);
}

// ---------------------------------------------------------------------------
extern "C" void kernel_launch(void* const* d_in, const int* in_sizes, int n_in,
                              void* d_out, int out_size) {
    const float* input = (const float*)d_in[0];
    const float* embed = (const float*)d_in[1];
    const float* pos   = (const float*)d_in[2];
    const float* cs    = (const float*)d_in[3];
    const float* ea    = (const float*)d_in[4];
    float* out = (float*)d_out;

    cudaFuncSetAttribute(vq_main, cudaFuncAttributeMaxDynamicSharedMemorySize,
                         SMEM_TOTAL);
    int full = (out_size >= OUT_FULL) ? 1 : 0;

    vq_prep0<<<2048, 256>>>(pos);
    vq_prep1<<<64, 256>>>(embed);
    vq_main<<<256, 256, SMEM_TOTAL>>>(input, out, full);
    if (full) {
        vq_fin1<<<NCODES / 256, 256>>>(cs, out);
        vq_fin2<<<(64 * NCODES) / 256, 256>>>(ea, out);
    }
}